// round 1
// baseline (speedup 1.0000x reference)
#include <cuda_runtime.h>
#include <cuda_bf16.h>

#define FULL_MASK 0xFFFFFFFFu

constexpr int E_EDGES = 65536;
constexpr int F_DIM   = 128;
constexpr int D_DEG   = 32;

// One warp per edge.
//   lane l owns feature channels [4l, 4l+4) as a float4, and neighbor slot l.
// out[e] = sum_f xi[f]*xj[f]*W[f]  +  sum_{d: ni[d] in nj} dot(x[ni[d]], W[F:2F])  +  b
__global__ void __launch_bounds__(256, 8)
ncn_kernel(const float* __restrict__ x,
           const int*   __restrict__ nbr,
           const int*   __restrict__ tar_ei,
           const float* __restrict__ W,
           const float* __restrict__ b,
           float*       __restrict__ out)
{
    const int lane    = threadIdx.x & 31;
    const int warp_id = (blockIdx.x * blockDim.x + threadIdx.x) >> 5;
    const int n_warps = (gridDim.x * blockDim.x) >> 5;

    // Per-lane weight slices (W is [256,1] contiguous): W0 = W[0:128], W1 = W[128:256]
    const float4 w0 = reinterpret_cast<const float4*>(W)[lane];
    const float4 w1 = reinterpret_cast<const float4*>(W + F_DIM)[lane];
    const float  bv = __ldg(b);

    for (int e = warp_id; e < E_EDGES; e += n_warps) {
        const int i = __ldg(tar_ei + e);            // tar_ei[0][e]
        const int j = __ldg(tar_ei + E_EDGES + e);  // tar_ei[1][e]

        // Gather endpoint features: 512B per row, fully coalesced across the warp.
        const float4 a = reinterpret_cast<const float4*>(x + (size_t)i * F_DIM)[lane];
        const float4 c = reinterpret_cast<const float4*>(x + (size_t)j * F_DIM)[lane];

        // Neighbor lists, one entry per lane (128B coalesced per row).
        const int ni_l = __ldg(nbr + (size_t)i * D_DEG + lane);
        const int nj_l = __ldg(nbr + (size_t)j * D_DEG + lane);

        // (xi * xj) . W0, per-lane partial
        float acc = a.x*c.x*w0.x + a.y*c.y*w0.y + a.z*c.z*w0.z + a.w*c.w*w0.w;

        // lower_bound of ni_l in the sorted distributed nj (clip to D-1, matching
        // jnp.searchsorted + clip + equality test in the reference).
        int lo = 0, hi = D_DEG - 1;
        #pragma unroll
        for (int s = 0; s < 5; ++s) {
            const int mid = (lo + hi) >> 1;
            const int v   = __shfl_sync(FULL_MASK, nj_l, mid);
            if (v < ni_l) lo = mid + 1; else hi = mid;
        }
        const bool hit = (__shfl_sync(FULL_MASK, nj_l, lo) == ni_l);

        // Rare common-neighbor hits: warp cooperatively accumulates dot(x[cn], W1).
        // hm is warp-uniform (ballot), so the loop and shuffles stay converged.
        unsigned hm = __ballot_sync(FULL_MASK, hit);
        while (hm) {
            const int h = __ffs(hm) - 1;
            hm &= hm - 1u;
            const int cn = __shfl_sync(FULL_MASK, ni_l, h);
            const float4 xc = reinterpret_cast<const float4*>(x + (size_t)cn * F_DIM)[lane];
            acc += xc.x*w1.x + xc.y*w1.y + xc.z*w1.z + xc.w*w1.w;
        }

        // Warp reduction
        #pragma unroll
        for (int off = 16; off >= 1; off >>= 1)
            acc += __shfl_down_sync(FULL_MASK, acc, off);

        if (lane == 0) out[e] = acc + bv;
    }
}

extern "C" void kernel_launch(void* const* d_in, const int* in_sizes, int n_in,
                              void* d_out, int out_size)
{
    const float* x      = (const float*)d_in[0];
    const int*   nbr    = (const int*)  d_in[1];
    const int*   tar_ei = (const int*)  d_in[2];
    const float* W      = (const float*)d_in[3];
    const float* b      = (const float*)d_in[4];
    float*       out    = (float*)d_out;

    // 8 warps/block; ~7 edges per warp via grid-stride (amortizes weight-register setup).
    ncn_kernel<<<1184, 256>>>(x, nbr, tar_ei, W, b, out);
}